// round 1
// baseline (speedup 1.0000x reference)
#include <cuda_runtime.h>
#include <math.h>

// Problem constants
#define S_LEN   2048
#define BATCH   2
#define NHEAD   16
#define HDIM    128
#define DMODEL  2048
#define INNER   2048          // NHEAD*HDIM
#define ROWS    (BATCH*S_LEN) // 4096

// Scratch buffers (allocation is forbidden -> __device__ globals)
__device__ float g_q[(size_t)ROWS * INNER];
__device__ float g_k[(size_t)ROWS * INNER];
__device__ float g_v[(size_t)ROWS * INNER];
__device__ float g_ao[(size_t)ROWS * INNER];

// ---------------------------------------------------------------------------
// SGEMM: C[M,N] = A[M,K] @ B[K,N], all row-major fp32.
// 128x128 block tile, BK=16, 256 threads, 8x8 per-thread microtile.
// ---------------------------------------------------------------------------
#define BM 128
#define BN 128
#define BK 16

__global__ __launch_bounds__(256, 2)
void sgemm_kernel(const float* __restrict__ A, const float* __restrict__ B,
                  float* __restrict__ C, int M, int N, int K) {
    __shared__ float As[BK][BM + 4];   // stored transposed: As[k][m]
    __shared__ float Bs[BK][BN + 4];

    const int tid = threadIdx.x;
    const int tx = tid & 15;
    const int ty = tid >> 4;
    const int row0 = blockIdx.y * BM;
    const int col0 = blockIdx.x * BN;

    float acc[8][8];
#pragma unroll
    for (int i = 0; i < 8; i++)
#pragma unroll
        for (int j = 0; j < 8; j++) acc[i][j] = 0.0f;

    for (int k0 = 0; k0 < K; k0 += BK) {
        // Load A tile (128x16) and B tile (16x128); 512 float4 each.
#pragma unroll
        for (int i = 0; i < 2; i++) {
            int idx = tid + i * 256;
            int m  = idx >> 2;
            int kv = (idx & 3) << 2;
            float4 a = *(const float4*)(A + (size_t)(row0 + m) * K + k0 + kv);
            As[kv + 0][m] = a.x;
            As[kv + 1][m] = a.y;
            As[kv + 2][m] = a.z;
            As[kv + 3][m] = a.w;

            int kb = idx >> 5;
            int nv = (idx & 31) << 2;
            float4 b = *(const float4*)(B + (size_t)(k0 + kb) * N + col0 + nv);
            *(float4*)&Bs[kb][nv] = b;
        }
        __syncthreads();

#pragma unroll
        for (int kk = 0; kk < BK; kk++) {
            float ar[8], br[8];
            *(float4*)&ar[0] = *(float4*)&As[kk][ty * 8];
            *(float4*)&ar[4] = *(float4*)&As[kk][ty * 8 + 4];
            *(float4*)&br[0] = *(float4*)&Bs[kk][tx * 8];
            *(float4*)&br[4] = *(float4*)&Bs[kk][tx * 8 + 4];
#pragma unroll
            for (int i = 0; i < 8; i++)
#pragma unroll
                for (int j = 0; j < 8; j++)
                    acc[i][j] += ar[i] * br[j];
        }
        __syncthreads();
    }

#pragma unroll
    for (int i = 0; i < 8; i++) {
        float* crow = C + (size_t)(row0 + ty * 8 + i) * N + col0 + tx * 8;
        *(float4*)(crow)     = make_float4(acc[i][0], acc[i][1], acc[i][2], acc[i][3]);
        *(float4*)(crow + 4) = make_float4(acc[i][4], acc[i][5], acc[i][6], acc[i][7]);
    }
}

// ---------------------------------------------------------------------------
// Per-head RMSNorm: data viewed as [nrows, 128]; one warp per row.
// ---------------------------------------------------------------------------
__global__ void rmsnorm_kernel(float* __restrict__ data,
                               const float* __restrict__ gamma, int nrows) {
    int warp = (blockIdx.x * blockDim.x + threadIdx.x) >> 5;
    int lane = threadIdx.x & 31;
    if (warp >= nrows) return;
    float* row = data + (size_t)warp * HDIM;
    float4 v = *(float4*)(row + lane * 4);
    float ss = v.x * v.x + v.y * v.y + v.z * v.z + v.w * v.w;
#pragma unroll
    for (int o = 16; o > 0; o >>= 1)
        ss += __shfl_xor_sync(0xffffffffu, ss, o);
    float r = rsqrtf(ss * (1.0f / (float)HDIM) + 1e-6f);
    float4 g = *(const float4*)(gamma + lane * 4);
    v.x *= r * g.x; v.y *= r * g.y; v.z *= r * g.z; v.w *= r * g.w;
    *(float4*)(row + lane * 4) = v;
}

// ---------------------------------------------------------------------------
// Flash attention (fp32, non-causal). Layout of q/k/v: [B, S, H, Dh] i.e.
// row stride INNER, head h occupies columns [h*128, h*128+128).
// CTA: 256 threads, BLOCK_M=64 queries, BLOCK_N=64 keys per iteration.
// Per-thread: S-frag rows ty*4+i (i<4), cols tx+16j (j<4);
//             O-frag rows ty*4+i, cols tx*4+r (+64*cc), r<4, cc<2.
// smem: Qs[64][128], Ks[64][132] (padded), Vs[64][128], Ps[64][64]
// ---------------------------------------------------------------------------
#define BLK_M 64
#define BLK_N 64
#define KLD   132   // padded leading dim for K tile

__global__ __launch_bounds__(256, 2)
void flash_kernel(const float* __restrict__ Q, const float* __restrict__ K,
                  const float* __restrict__ V, float* __restrict__ O) {
    extern __shared__ float sm[];
    float* Qs = sm;                       // 64*128 = 8192
    float* Ks = sm + 8192;                // 64*132 = 8448
    float* Vs = sm + 8192 + 8448;         // 64*128 = 8192
    float* Ps = sm + 8192 + 8448 + 8192;  // 64*64  = 4096

    const int tid = threadIdx.x;
    const int tx = tid & 15;
    const int ty = tid >> 4;
    const int mblk = blockIdx.x;
    const int h = blockIdx.y;
    const int b = blockIdx.z;

    const float* Qg = Q + ((size_t)(b * S_LEN + mblk * BLK_M)) * INNER + h * HDIM;
    const float* Kg = K + ((size_t)(b * S_LEN)) * INNER + h * HDIM;
    const float* Vg = V + ((size_t)(b * S_LEN)) * INNER + h * HDIM;
    float*       Og = O + ((size_t)(b * S_LEN + mblk * BLK_M)) * INNER + h * HDIM;

    // Load Q tile: 64x128 -> 2048 float4
#pragma unroll
    for (int i = 0; i < 8; i++) {
        int idx = tid + i * 256;
        int m  = idx >> 5;
        int dv = (idx & 31) << 2;
        *(float4*)&Qs[m * HDIM + dv] = *(const float4*)(Qg + (size_t)m * INNER + dv);
    }

    float m_i[4], l_i[4], acc[4][8];
#pragma unroll
    for (int i = 0; i < 4; i++) {
        m_i[i] = -1e30f;
        l_i[i] = 0.0f;
#pragma unroll
        for (int j = 0; j < 8; j++) acc[i][j] = 0.0f;
    }
    const float scale = 0.08838834764831845f; // 1/sqrt(128)

    for (int n0 = 0; n0 < S_LEN; n0 += BLK_N) {
        // Load K (padded ld) and V tiles
#pragma unroll
        for (int i = 0; i < 8; i++) {
            int idx = tid + i * 256;
            int n  = idx >> 5;
            int dv = (idx & 31) << 2;
            *(float4*)&Ks[n * KLD  + dv] = *(const float4*)(Kg + (size_t)(n0 + n) * INNER + dv);
            *(float4*)&Vs[n * HDIM + dv] = *(const float4*)(Vg + (size_t)(n0 + n) * INNER + dv);
        }
        __syncthreads();

        // S = Q @ K^T  (raw, scale applied after)
        float s[4][4];
#pragma unroll
        for (int i = 0; i < 4; i++)
#pragma unroll
            for (int j = 0; j < 4; j++) s[i][j] = 0.0f;

#pragma unroll 8
        for (int d = 0; d < HDIM; d += 4) {
            float4 qa[4], kb[4];
#pragma unroll
            for (int i = 0; i < 4; i++)
                qa[i] = *(float4*)&Qs[(ty * 4 + i) * HDIM + d];
#pragma unroll
            for (int j = 0; j < 4; j++)
                kb[j] = *(float4*)&Ks[(tx + 16 * j) * KLD + d];
#pragma unroll
            for (int i = 0; i < 4; i++)
#pragma unroll
                for (int j = 0; j < 4; j++) {
                    s[i][j] += qa[i].x * kb[j].x;
                    s[i][j] += qa[i].y * kb[j].y;
                    s[i][j] += qa[i].z * kb[j].z;
                    s[i][j] += qa[i].w * kb[j].w;
                }
        }

        // Online softmax update (rows reduced across the 16-lane tx group)
        float p[4][4];
#pragma unroll
        for (int i = 0; i < 4; i++) {
            float tmax = s[i][0] * scale;
#pragma unroll
            for (int j = 1; j < 4; j++) tmax = fmaxf(tmax, s[i][j] * scale);
#pragma unroll
            for (int o = 1; o < 16; o <<= 1)
                tmax = fmaxf(tmax, __shfl_xor_sync(0xffffffffu, tmax, o));
            float m_new = fmaxf(m_i[i], tmax);
            float alpha = __expf(m_i[i] - m_new);
            float rsum = 0.0f;
#pragma unroll
            for (int j = 0; j < 4; j++) {
                p[i][j] = __expf(s[i][j] * scale - m_new);
                rsum += p[i][j];
            }
#pragma unroll
            for (int o = 1; o < 16; o <<= 1)
                rsum += __shfl_xor_sync(0xffffffffu, rsum, o);
            l_i[i] = l_i[i] * alpha + rsum;
            m_i[i] = m_new;
#pragma unroll
            for (int j = 0; j < 8; j++) acc[i][j] *= alpha;
        }

        // Publish P
#pragma unroll
        for (int i = 0; i < 4; i++)
#pragma unroll
            for (int j = 0; j < 4; j++)
                Ps[(ty * 4 + i) * BLK_N + tx + 16 * j] = p[i][j];
        __syncthreads();

        // O += P @ V
#pragma unroll 4
        for (int n = 0; n < BLK_N; n += 4) {
            float pa[4][4];
#pragma unroll
            for (int i = 0; i < 4; i++)
                *(float4*)pa[i] = *(const float4*)&Ps[(ty * 4 + i) * BLK_N + n];
#pragma unroll
            for (int r = 0; r < 4; r++) {
                float4 v0 = *(const float4*)&Vs[(n + r) * HDIM + tx * 4];
                float4 v1 = *(const float4*)&Vs[(n + r) * HDIM + tx * 4 + 64];
#pragma unroll
                for (int i = 0; i < 4; i++) {
                    float pv = pa[i][r];
                    acc[i][0] += pv * v0.x; acc[i][1] += pv * v0.y;
                    acc[i][2] += pv * v0.z; acc[i][3] += pv * v0.w;
                    acc[i][4] += pv * v1.x; acc[i][5] += pv * v1.y;
                    acc[i][6] += pv * v1.z; acc[i][7] += pv * v1.w;
                }
            }
        }
        __syncthreads();
    }

    // Epilogue: normalize by l and store
#pragma unroll
    for (int i = 0; i < 4; i++) {
        float inv = 1.0f / l_i[i];
        float* orow = Og + (size_t)(ty * 4 + i) * INNER;
        *(float4*)(orow + tx * 4) =
            make_float4(acc[i][0] * inv, acc[i][1] * inv, acc[i][2] * inv, acc[i][3] * inv);
        *(float4*)(orow + tx * 4 + 64) =
            make_float4(acc[i][4] * inv, acc[i][5] * inv, acc[i][6] * inv, acc[i][7] * inv);
    }
}

// ---------------------------------------------------------------------------
// Launcher
// ---------------------------------------------------------------------------
extern "C" void kernel_launch(void* const* d_in, const int* in_sizes, int n_in,
                              void* d_out, int out_size) {
    const float* x  = (const float*)d_in[0];
    const float* Wq = (const float*)d_in[1];
    const float* Wk = (const float*)d_in[2];
    const float* Wv = (const float*)d_in[3];
    const float* Wo = (const float*)d_in[4];
    const float* qg = (const float*)d_in[5];
    const float* kg = (const float*)d_in[6];
    float* out = (float*)d_out;

    float *dq, *dk, *dv, *dao;
    cudaGetSymbolAddress((void**)&dq,  g_q);
    cudaGetSymbolAddress((void**)&dk,  g_k);
    cudaGetSymbolAddress((void**)&dv,  g_v);
    cudaGetSymbolAddress((void**)&dao, g_ao);

    dim3 gridG(INNER / BN, ROWS / BM);  // (16, 32)

    // QKV projections
    sgemm_kernel<<<gridG, 256>>>(x, Wq, dq, ROWS, INNER, DMODEL);
    sgemm_kernel<<<gridG, 256>>>(x, Wk, dk, ROWS, INNER, DMODEL);
    sgemm_kernel<<<gridG, 256>>>(x, Wv, dv, ROWS, INNER, DMODEL);

    // Per-head RMSNorm on q and k
    int nrows = ROWS * NHEAD;              // 65536 rows of 128
    int rb = (nrows * 32 + 255) / 256;     // warps -> blocks of 8 warps
    rmsnorm_kernel<<<rb, 256>>>(dq, qg, nrows);
    rmsnorm_kernel<<<rb, 256>>>(dk, kg, nrows);

    // Flash attention
    size_t fa_smem = (size_t)(64 * 128 + 64 * KLD + 64 * 128 + 64 * 64) * sizeof(float);
    cudaFuncSetAttribute(flash_kernel, cudaFuncAttributeMaxDynamicSharedMemorySize,
                         (int)fa_smem);
    dim3 gridF(S_LEN / BLK_M, NHEAD, BATCH);  // (32, 16, 2)
    flash_kernel<<<gridF, 256, fa_smem>>>(dq, dk, dv, dao);

    // Output projection -> d_out
    sgemm_kernel<<<gridG, 256>>>(dao, Wo, out, ROWS, DMODEL, INNER);
}

// round 3
// speedup vs baseline: 1.5573x; 1.5573x over previous
#include <cuda_runtime.h>
#include <cuda_bf16.h>
#include <stdint.h>
#include <math.h>

// Problem constants
#define S_LEN   2048
#define BATCH   2
#define NHEAD   16
#define HDIM    128
#define DMODEL  2048
#define INNER   2048          // NHEAD*HDIM
#define ROWS    (BATCH*S_LEN) // 4096

// Scratch (allocation forbidden -> __device__ globals)
__device__ float g_q[(size_t)ROWS * INNER];
__device__ float g_k[(size_t)ROWS * INNER];
__device__ float g_v[(size_t)ROWS * INNER];
__device__ float g_ao[(size_t)ROWS * INNER];
__device__ __nv_bfloat16 g_xhi[(size_t)ROWS * DMODEL];
__device__ __nv_bfloat16 g_xlo[(size_t)ROWS * DMODEL];
__device__ __nv_bfloat16 g_wthi[4][(size_t)DMODEL * INNER];  // W^T per matrix, [N,K]
__device__ __nv_bfloat16 g_wtlo[4][(size_t)DMODEL * INNER];
__device__ __nv_bfloat16 g_aohi[(size_t)ROWS * INNER];
__device__ __nv_bfloat16 g_aolo[(size_t)ROWS * INNER];

// ---------------------------------------------------------------------------
// Helpers (base PTX only: cp.async / ldmatrix / mma.sync — no tcgen05)
// ---------------------------------------------------------------------------
__device__ __forceinline__ uint32_t smem_u32(const void* p) {
    uint32_t a;
    asm("{ .reg .u64 t; cvta.to.shared.u64 t, %1; cvt.u32.u64 %0, t; }"
        : "=r"(a) : "l"(p));
    return a;
}
__device__ __forceinline__ void cp16(uint32_t dst, const void* src) {
    asm volatile("cp.async.cg.shared.global [%0], [%1], 16;" :: "r"(dst), "l"(src));
}
__device__ __forceinline__ void cp_commit() { asm volatile("cp.async.commit_group;"); }
template<int N> __device__ __forceinline__ void cp_wait() {
    asm volatile("cp.async.wait_group %0;" :: "n"(N));
}
__device__ __forceinline__ void ldm_x4(uint32_t* r, uint32_t addr) {
    asm volatile("ldmatrix.sync.aligned.m8n8.x4.shared.b16 {%0,%1,%2,%3}, [%4];"
                 : "=r"(r[0]), "=r"(r[1]), "=r"(r[2]), "=r"(r[3]) : "r"(addr));
}
__device__ __forceinline__ void mma16816(float* c, const uint32_t* a, const uint32_t* b) {
    asm volatile(
        "mma.sync.aligned.m16n8k16.row.col.f32.bf16.bf16.f32 "
        "{%0,%1,%2,%3}, {%4,%5,%6,%7}, {%8,%9}, {%0,%1,%2,%3};"
        : "+f"(c[0]), "+f"(c[1]), "+f"(c[2]), "+f"(c[3])
        : "r"(a[0]), "r"(a[1]), "r"(a[2]), "r"(a[3]), "r"(b[0]), "r"(b[1]));
}

// ---------------------------------------------------------------------------
// bf16 hi/lo split GEMM on mma.sync: C[M,N] = A[M,K] @ Bt[N,K]^T (fp32 out)
// computing Ahi*Bhi + Ahi*Blo + Alo*Bhi with fp32 accumulation.
// CTA 128x128, BK=32, 256 threads (8 warps as 4x2, warp tile 32x64),
// double-buffered cp.async smem; smem rows are 40 bf16 (80 B) so that the
// 8 rows of each ldmatrix land in distinct 16B bank groups (5 mod 8 walk).
// ---------------------------------------------------------------------------
#define G_BM 128
#define G_BN 128
#define G_BK 32
#define ROWB 80                       // smem row stride in bytes (40 bf16)
#define TILEB (128 * ROWB)            // 10240 B per tile
#define STAGEB (4 * TILEB)            // Ahi,Alo,Bhi,Blo
#define GEMM_SMEM (2 * STAGEB)        // 81920 B

__global__ __launch_bounds__(256, 1)
void gemm_mma_kernel(const __nv_bfloat16* __restrict__ Ahi,
                     const __nv_bfloat16* __restrict__ Alo,
                     const __nv_bfloat16* __restrict__ Bhi,
                     const __nv_bfloat16* __restrict__ Blo,
                     float* __restrict__ C, int M, int N, int K)
{
    extern __shared__ char smem[];
    const uint32_t sbase = smem_u32(smem);
    const int tid  = threadIdx.x;
    const int warp = tid >> 5;
    const int lane = tid & 31;
    const int wm = warp >> 1;          // 0..3 -> 32 rows each
    const int wn = warp & 1;           // 0..1 -> 64 cols each

    const int row0 = blockIdx.y * G_BM;
    const int col0 = blockIdx.x * G_BN;
    const size_t Kb = (size_t)K * 2;   // row bytes in gmem

    const char* gp[4] = {
        (const char*)Ahi + (size_t)row0 * Kb,
        (const char*)Alo + (size_t)row0 * Kb,
        (const char*)Bhi + (size_t)col0 * Kb,
        (const char*)Blo + (size_t)col0 * Kb
    };

    float acc[2][8][4];
#pragma unroll
    for (int mt = 0; mt < 2; mt++)
#pragma unroll
        for (int nt = 0; nt < 8; nt++)
#pragma unroll
            for (int r = 0; r < 4; r++) acc[mt][nt][r] = 0.0f;

    const int NCH = K / G_BK;

    auto load_chunk = [&](int c, int s) {
        size_t koff = (size_t)c * (G_BK * 2);   // byte offset into each row
        uint32_t stb = sbase + s * STAGEB;
#pragma unroll
        for (int t = 0; t < 4; t++) {
            uint32_t tb = stb + t * TILEB;
            const char* g = gp[t];
#pragma unroll
            for (int i = 0; i < 2; i++) {
                int idx = i * 256 + tid;            // 0..511
                int row = idx >> 2;                 // 0..127
                int ks  = idx & 3;                  // 16B segment
                cp16(tb + row * ROWB + ks * 16,
                     g + (size_t)row * Kb + koff + ks * 16);
            }
        }
    };

    load_chunk(0, 0);
    cp_commit();

    for (int c = 0; c < NCH; ++c) {
        const int buf = c & 1;
        cp_wait<0>();
        __syncthreads();
        if (c + 1 < NCH) {
            load_chunk(c + 1, buf ^ 1);
            cp_commit();
        }

        const uint32_t base = sbase + buf * STAGEB;
#pragma unroll
        for (int ks = 0; ks < 2; ks++) {
            // A fragments (hi & lo), 2 m-tiles of 16
            uint32_t ah[2][4], al[2][4];
#pragma unroll
            for (int mt = 0; mt < 2; mt++) {
                uint32_t arow = wm * 32 + mt * 16 + (lane & 15);
                uint32_t aoff = arow * ROWB + (ks * 16 + 8 * (lane >> 4)) * 2;
                ldm_x4(ah[mt], base + aoff);
                ldm_x4(al[mt], base + TILEB + aoff);
            }
            // B fragments (hi & lo), 8 n-tiles of 8 (fetched as 4 x4-loads)
            uint32_t bh[8][2], bl[8][2];
#pragma unroll
            for (int p = 0; p < 4; p++) {
                uint32_t brow = wn * 64 + p * 16 + (lane & 7) + 8 * (lane >> 4);
                uint32_t boff = brow * ROWB + (ks * 16 + 8 * ((lane >> 3) & 1)) * 2;
                uint32_t t0[4], t1[4];
                ldm_x4(t0, base + 2 * TILEB + boff);
                ldm_x4(t1, base + 3 * TILEB + boff);
                bh[2*p][0]   = t0[0]; bh[2*p][1]   = t0[1];
                bh[2*p+1][0] = t0[2]; bh[2*p+1][1] = t0[3];
                bl[2*p][0]   = t1[0]; bl[2*p][1]   = t1[1];
                bl[2*p+1][0] = t1[2]; bl[2*p+1][1] = t1[3];
            }
            // hh + hl + lh
#pragma unroll
            for (int mt = 0; mt < 2; mt++)
#pragma unroll
                for (int nt = 0; nt < 8; nt++) {
                    mma16816(acc[mt][nt], ah[mt], bh[nt]);
                    mma16816(acc[mt][nt], ah[mt], bl[nt]);
                    mma16816(acc[mt][nt], al[mt], bh[nt]);
                }
        }
        __syncthreads();
    }

    // Epilogue
#pragma unroll
    for (int mt = 0; mt < 2; mt++) {
        int r0 = row0 + wm * 32 + mt * 16 + (lane >> 2);
#pragma unroll
        for (int nt = 0; nt < 8; nt++) {
            int cc = col0 + wn * 64 + nt * 8 + (lane & 3) * 2;
            *(float2*)(C + (size_t)r0 * N + cc) =
                make_float2(acc[mt][nt][0], acc[mt][nt][1]);
            *(float2*)(C + (size_t)(r0 + 8) * N + cc) =
                make_float2(acc[mt][nt][2], acc[mt][nt][3]);
        }
    }
}

// ---------------------------------------------------------------------------
// fp32 -> bf16 hi/lo split (elementwise, vectorized by 4)
// ---------------------------------------------------------------------------
__global__ void split_kernel(const float4* __restrict__ in,
                             __nv_bfloat16* __restrict__ hi,
                             __nv_bfloat16* __restrict__ lo, int n4) {
    int i = blockIdx.x * blockDim.x + threadIdx.x;
    if (i >= n4) return;
    float4 v = in[i];
    float f[4] = { v.x, v.y, v.z, v.w };
    __nv_bfloat16 h[4], l[4];
#pragma unroll
    for (int j = 0; j < 4; j++) {
        h[j] = __float2bfloat16(f[j]);
        l[j] = __float2bfloat16(f[j] - __bfloat162float(h[j]));
    }
    *(uint2*)(hi + 4 * (size_t)i) = *(uint2*)h;
    *(uint2*)(lo + 4 * (size_t)i) = *(uint2*)l;
}

// ---------------------------------------------------------------------------
// Transpose + split: W[K=2048, N=2048] fp32 -> T{hi,lo}[N, K] bf16
// ---------------------------------------------------------------------------
__global__ void transpose_split_kernel(const float* __restrict__ W,
                                       __nv_bfloat16* __restrict__ Thi,
                                       __nv_bfloat16* __restrict__ Tlo) {
    __shared__ float t[32][33];
    int n0 = blockIdx.x * 32, k0 = blockIdx.y * 32;
#pragma unroll
    for (int i = 0; i < 32; i += 8)
        t[threadIdx.y + i][threadIdx.x] =
            W[(size_t)(k0 + threadIdx.y + i) * 2048 + n0 + threadIdx.x];
    __syncthreads();
#pragma unroll
    for (int i = 0; i < 32; i += 8) {
        float v = t[threadIdx.x][threadIdx.y + i];
        __nv_bfloat16 h = __float2bfloat16(v);
        __nv_bfloat16 l = __float2bfloat16(v - __bfloat162float(h));
        size_t o = (size_t)(n0 + threadIdx.y + i) * 2048 + k0 + threadIdx.x;
        Thi[o] = h;
        Tlo[o] = l;
    }
}

// ---------------------------------------------------------------------------
// Per-head RMSNorm: [nrows, 128]; one warp per row.
// ---------------------------------------------------------------------------
__global__ void rmsnorm_kernel(float* __restrict__ data,
                               const float* __restrict__ gamma, int nrows) {
    int warp = (blockIdx.x * blockDim.x + threadIdx.x) >> 5;
    int lane = threadIdx.x & 31;
    if (warp >= nrows) return;
    float* row = data + (size_t)warp * HDIM;
    float4 v = *(float4*)(row + lane * 4);
    float ss = v.x * v.x + v.y * v.y + v.z * v.z + v.w * v.w;
#pragma unroll
    for (int o = 16; o > 0; o >>= 1)
        ss += __shfl_xor_sync(0xffffffffu, ss, o);
    float r = rsqrtf(ss * (1.0f / (float)HDIM) + 1e-6f);
    float4 g = *(const float4*)(gamma + lane * 4);
    v.x *= r * g.x; v.y *= r * g.y; v.z *= r * g.z; v.w *= r * g.w;
    *(float4*)(row + lane * 4) = v;
}

// ---------------------------------------------------------------------------
// Flash attention (fp32, non-causal) — unchanged (known correct).
// ---------------------------------------------------------------------------
#define BLK_M 64
#define BLK_N 64
#define KLD   132

__global__ __launch_bounds__(256, 2)
void flash_kernel(const float* __restrict__ Q, const float* __restrict__ K,
                  const float* __restrict__ V, float* __restrict__ O) {
    extern __shared__ float sm[];
    float* Qs = sm;
    float* Ks = sm + 8192;
    float* Vs = sm + 8192 + 8448;
    float* Ps = sm + 8192 + 8448 + 8192;

    const int tid = threadIdx.x;
    const int tx = tid & 15;
    const int ty = tid >> 4;
    const int mblk = blockIdx.x;
    const int h = blockIdx.y;
    const int b = blockIdx.z;

    const float* Qg = Q + ((size_t)(b * S_LEN + mblk * BLK_M)) * INNER + h * HDIM;
    const float* Kg = K + ((size_t)(b * S_LEN)) * INNER + h * HDIM;
    const float* Vg = V + ((size_t)(b * S_LEN)) * INNER + h * HDIM;
    float*       Og = O + ((size_t)(b * S_LEN + mblk * BLK_M)) * INNER + h * HDIM;

#pragma unroll
    for (int i = 0; i < 8; i++) {
        int idx = tid + i * 256;
        int m  = idx >> 5;
        int dv = (idx & 31) << 2;
        *(float4*)&Qs[m * HDIM + dv] = *(const float4*)(Qg + (size_t)m * INNER + dv);
    }

    float m_i[4], l_i[4], acc[4][8];
#pragma unroll
    for (int i = 0; i < 4; i++) {
        m_i[i] = -1e30f;
        l_i[i] = 0.0f;
#pragma unroll
        for (int j = 0; j < 8; j++) acc[i][j] = 0.0f;
    }
    const float scale = 0.08838834764831845f;

    for (int n0 = 0; n0 < S_LEN; n0 += BLK_N) {
#pragma unroll
        for (int i = 0; i < 8; i++) {
            int idx = tid + i * 256;
            int n  = idx >> 5;
            int dv = (idx & 31) << 2;
            *(float4*)&Ks[n * KLD  + dv] = *(const float4*)(Kg + (size_t)(n0 + n) * INNER + dv);
            *(float4*)&Vs[n * HDIM + dv] = *(const float4*)(Vg + (size_t)(n0 + n) * INNER + dv);
        }
        __syncthreads();

        float s[4][4];
#pragma unroll
        for (int i = 0; i < 4; i++)
#pragma unroll
            for (int j = 0; j < 4; j++) s[i][j] = 0.0f;

#pragma unroll 8
        for (int d = 0; d < HDIM; d += 4) {
            float4 qa[4], kb[4];
#pragma unroll
            for (int i = 0; i < 4; i++)
                qa[i] = *(float4*)&Qs[(ty * 4 + i) * HDIM + d];
#pragma unroll
            for (int j = 0; j < 4; j++)
                kb[j] = *(float4*)&Ks[(tx + 16 * j) * KLD + d];
#pragma unroll
            for (int i = 0; i < 4; i++)
#pragma unroll
                for (int j = 0; j < 4; j++) {
                    s[i][j] += qa[i].x * kb[j].x;
                    s[i][j] += qa[i].y * kb[j].y;
                    s[i][j] += qa[i].z * kb[j].z;
                    s[i][j] += qa[i].w * kb[j].w;
                }
        }

        float p[4][4];
#pragma unroll
        for (int i = 0; i < 4; i++) {
            float tmax = s[i][0] * scale;
#pragma unroll
            for (int j = 1; j < 4; j++) tmax = fmaxf(tmax, s[i][j] * scale);
#pragma unroll
            for (int o = 1; o < 16; o <<= 1)
                tmax = fmaxf(tmax, __shfl_xor_sync(0xffffffffu, tmax, o));
            float m_new = fmaxf(m_i[i], tmax);
            float alpha = __expf(m_i[i] - m_new);
            float rsum = 0.0f;
#pragma unroll
            for (int j = 0; j < 4; j++) {
                p[i][j] = __expf(s[i][j] * scale - m_new);
                rsum += p[i][j];
            }
#pragma unroll
            for (int o = 1; o < 16; o <<= 1)
                rsum += __shfl_xor_sync(0xffffffffu, rsum, o);
            l_i[i] = l_i[i] * alpha + rsum;
            m_i[i] = m_new;
#pragma unroll
            for (int j = 0; j < 8; j++) acc[i][j] *= alpha;
        }

#pragma unroll
        for (int i = 0; i < 4; i++)
#pragma unroll
            for (int j = 0; j < 4; j++)
                Ps[(ty * 4 + i) * BLK_N + tx + 16 * j] = p[i][j];
        __syncthreads();

#pragma unroll 4
        for (int n = 0; n < BLK_N; n += 4) {
            float pa[4][4];
#pragma unroll
            for (int i = 0; i < 4; i++)
                *(float4*)pa[i] = *(const float4*)&Ps[(ty * 4 + i) * BLK_N + n];
#pragma unroll
            for (int r = 0; r < 4; r++) {
                float4 v0 = *(const float4*)&Vs[(n + r) * HDIM + tx * 4];
                float4 v1 = *(const float4*)&Vs[(n + r) * HDIM + tx * 4 + 64];
#pragma unroll
                for (int i = 0; i < 4; i++) {
                    float pv = pa[i][r];
                    acc[i][0] += pv * v0.x; acc[i][1] += pv * v0.y;
                    acc[i][2] += pv * v0.z; acc[i][3] += pv * v0.w;
                    acc[i][4] += pv * v1.x; acc[i][5] += pv * v1.y;
                    acc[i][6] += pv * v1.z; acc[i][7] += pv * v1.w;
                }
            }
        }
        __syncthreads();
    }

#pragma unroll
    for (int i = 0; i < 4; i++) {
        float inv = 1.0f / l_i[i];
        float* orow = Og + (size_t)(ty * 4 + i) * INNER;
        *(float4*)(orow + tx * 4) =
            make_float4(acc[i][0] * inv, acc[i][1] * inv, acc[i][2] * inv, acc[i][3] * inv);
        *(float4*)(orow + tx * 4 + 64) =
            make_float4(acc[i][4] * inv, acc[i][5] * inv, acc[i][6] * inv, acc[i][7] * inv);
    }
}

// ---------------------------------------------------------------------------
// Launcher
// ---------------------------------------------------------------------------
extern "C" void kernel_launch(void* const* d_in, const int* in_sizes, int n_in,
                              void* d_out, int out_size) {
    const float* x  = (const float*)d_in[0];
    const float* Wq = (const float*)d_in[1];
    const float* Wk = (const float*)d_in[2];
    const float* Wv = (const float*)d_in[3];
    const float* Wo = (const float*)d_in[4];
    const float* qg = (const float*)d_in[5];
    const float* kg = (const float*)d_in[6];
    float* out = (float*)d_out;

    float *dq, *dk, *dv, *dao;
    __nv_bfloat16 *xhi, *xlo, *aohi, *aolo, *wthi, *wtlo;
    cudaGetSymbolAddress((void**)&dq,   g_q);
    cudaGetSymbolAddress((void**)&dk,   g_k);
    cudaGetSymbolAddress((void**)&dv,   g_v);
    cudaGetSymbolAddress((void**)&dao,  g_ao);
    cudaGetSymbolAddress((void**)&xhi,  g_xhi);
    cudaGetSymbolAddress((void**)&xlo,  g_xlo);
    cudaGetSymbolAddress((void**)&aohi, g_aohi);
    cudaGetSymbolAddress((void**)&aolo, g_aolo);
    cudaGetSymbolAddress((void**)&wthi, g_wthi);
    cudaGetSymbolAddress((void**)&wtlo, g_wtlo);
    const size_t WSZ = (size_t)DMODEL * INNER;

    // 1. Split x -> bf16 hi/lo
    int n4x = ROWS * DMODEL / 4;
    split_kernel<<<n4x / 256, 256>>>((const float4*)x, xhi, xlo, n4x);

    // 2. Transpose+split weights -> [N,K] bf16 hi/lo
    dim3 tb(32, 8), tg(64, 64);
    transpose_split_kernel<<<tg, tb>>>(Wq, wthi + 0*WSZ, wtlo + 0*WSZ);
    transpose_split_kernel<<<tg, tb>>>(Wk, wthi + 1*WSZ, wtlo + 1*WSZ);
    transpose_split_kernel<<<tg, tb>>>(Wv, wthi + 2*WSZ, wtlo + 2*WSZ);
    transpose_split_kernel<<<tg, tb>>>(Wo, wthi + 3*WSZ, wtlo + 3*WSZ);

    // 3. QKV projections on tensor cores (mma.sync path)
    cudaFuncSetAttribute(gemm_mma_kernel, cudaFuncAttributeMaxDynamicSharedMemorySize,
                         GEMM_SMEM);
    dim3 gg(INNER / G_BN, ROWS / G_BM);  // (16, 32)
    gemm_mma_kernel<<<gg, 256, GEMM_SMEM>>>(xhi, xlo, wthi + 0*WSZ, wtlo + 0*WSZ,
                                            dq, ROWS, INNER, DMODEL);
    gemm_mma_kernel<<<gg, 256, GEMM_SMEM>>>(xhi, xlo, wthi + 1*WSZ, wtlo + 1*WSZ,
                                            dk, ROWS, INNER, DMODEL);
    gemm_mma_kernel<<<gg, 256, GEMM_SMEM>>>(xhi, xlo, wthi + 2*WSZ, wtlo + 2*WSZ,
                                            dv, ROWS, INNER, DMODEL);

    // 4. Per-head RMSNorm on q and k
    int nrows = ROWS * NHEAD;
    int rb = (nrows * 32 + 255) / 256;
    rmsnorm_kernel<<<rb, 256>>>(dq, qg, nrows);
    rmsnorm_kernel<<<rb, 256>>>(dk, kg, nrows);

    // 5. Flash attention (fp32)
    size_t fa_smem = (size_t)(64 * 128 + 64 * KLD + 64 * 128 + 64 * 64) * sizeof(float);
    cudaFuncSetAttribute(flash_kernel, cudaFuncAttributeMaxDynamicSharedMemorySize,
                         (int)fa_smem);
    dim3 gridF(S_LEN / BLK_M, NHEAD, BATCH);
    flash_kernel<<<gridF, 256, fa_smem>>>(dq, dk, dv, dao);

    // 6. Split attention output, then output projection -> d_out
    int n4a = ROWS * INNER / 4;
    split_kernel<<<n4a / 256, 256>>>((const float4*)dao, aohi, aolo, n4a);
    gemm_mma_kernel<<<gg, 256, GEMM_SMEM>>>(aohi, aolo, wthi + 3*WSZ, wtlo + 3*WSZ,
                                            out, ROWS, DMODEL, INNER);
}

// round 4
// speedup vs baseline: 2.2858x; 1.4678x over previous
#include <cuda_runtime.h>
#include <cuda_bf16.h>
#include <stdint.h>
#include <math.h>

// Problem constants
#define S_LEN   2048
#define BATCH   2
#define NHEAD   16
#define HDIM    128
#define DMODEL  2048
#define INNER   2048          // NHEAD*HDIM
#define ROWS    (BATCH*S_LEN) // 4096

// Scratch (allocation forbidden -> __device__ globals)
__device__ float g_q[(size_t)ROWS * INNER];
__device__ float g_k[(size_t)ROWS * INNER];
__device__ float g_v[(size_t)ROWS * INNER];
__device__ __nv_bfloat16 g_xhi[(size_t)ROWS * DMODEL];
__device__ __nv_bfloat16 g_xlo[(size_t)ROWS * DMODEL];
__device__ __nv_bfloat16 g_wthi[4][(size_t)DMODEL * INNER];  // W^T per matrix, [N,K]
__device__ __nv_bfloat16 g_wtlo[4][(size_t)DMODEL * INNER];
__device__ __nv_bfloat16 g_qhi[(size_t)ROWS * INNER];
__device__ __nv_bfloat16 g_qlo[(size_t)ROWS * INNER];
__device__ __nv_bfloat16 g_khi[(size_t)ROWS * INNER];
__device__ __nv_bfloat16 g_klo[(size_t)ROWS * INNER];
__device__ __nv_bfloat16 g_vhi[(size_t)ROWS * INNER];
__device__ __nv_bfloat16 g_vlo[(size_t)ROWS * INNER];
__device__ __nv_bfloat16 g_aohi[(size_t)ROWS * INNER];
__device__ __nv_bfloat16 g_aolo[(size_t)ROWS * INNER];

// ---------------------------------------------------------------------------
// Helpers (base PTX only: cp.async / ldmatrix / mma.sync)
// ---------------------------------------------------------------------------
__device__ __forceinline__ uint32_t smem_u32(const void* p) {
    uint32_t a;
    asm("{ .reg .u64 t; cvta.to.shared.u64 t, %1; cvt.u32.u64 %0, t; }"
        : "=r"(a) : "l"(p));
    return a;
}
__device__ __forceinline__ void cp16(uint32_t dst, const void* src) {
    asm volatile("cp.async.cg.shared.global [%0], [%1], 16;" :: "r"(dst), "l"(src));
}
__device__ __forceinline__ void cp_commit() { asm volatile("cp.async.commit_group;"); }
template<int N> __device__ __forceinline__ void cp_wait() {
    asm volatile("cp.async.wait_group %0;" :: "n"(N));
}
__device__ __forceinline__ void ldm_x4(uint32_t* r, uint32_t addr) {
    asm volatile("ldmatrix.sync.aligned.m8n8.x4.shared.b16 {%0,%1,%2,%3}, [%4];"
                 : "=r"(r[0]), "=r"(r[1]), "=r"(r[2]), "=r"(r[3]) : "r"(addr));
}
__device__ __forceinline__ void ldm_x4t(uint32_t* r, uint32_t addr) {
    asm volatile("ldmatrix.sync.aligned.m8n8.x4.trans.shared.b16 {%0,%1,%2,%3}, [%4];"
                 : "=r"(r[0]), "=r"(r[1]), "=r"(r[2]), "=r"(r[3]) : "r"(addr));
}
__device__ __forceinline__ void mma16816(float* c, const uint32_t* a, const uint32_t* b) {
    asm volatile(
        "mma.sync.aligned.m16n8k16.row.col.f32.bf16.bf16.f32 "
        "{%0,%1,%2,%3}, {%4,%5,%6,%7}, {%8,%9}, {%0,%1,%2,%3};"
        : "+f"(c[0]), "+f"(c[1]), "+f"(c[2]), "+f"(c[3])
        : "r"(a[0]), "r"(a[1]), "r"(a[2]), "r"(a[3]), "r"(b[0]), "r"(b[1]));
}
__device__ __forceinline__ uint32_t pack_bf2(float a, float b) {
    __nv_bfloat162 t = __floats2bfloat162_rn(a, b);
    return *(uint32_t*)&t;
}

// ---------------------------------------------------------------------------
// bf16 hi/lo split GEMM: C[M,N] = A[M,K] @ Bt[N,K]^T (fp32 out), hh+hl+lh.
// ---------------------------------------------------------------------------
#define G_BM 128
#define G_BN 128
#define G_BK 32
#define ROWB 80
#define TILEB (128 * ROWB)
#define STAGEB (4 * TILEB)
#define GEMM_SMEM (2 * STAGEB)

__global__ __launch_bounds__(256, 1)
void gemm_mma_kernel(const __nv_bfloat16* __restrict__ Ahi,
                     const __nv_bfloat16* __restrict__ Alo,
                     const __nv_bfloat16* __restrict__ Bhi,
                     const __nv_bfloat16* __restrict__ Blo,
                     float* __restrict__ C, int M, int N, int K)
{
    extern __shared__ char smem[];
    const uint32_t sbase = smem_u32(smem);
    const int tid  = threadIdx.x;
    const int warp = tid >> 5;
    const int lane = tid & 31;
    const int wm = warp >> 1;
    const int wn = warp & 1;

    const int row0 = blockIdx.y * G_BM;
    const int col0 = blockIdx.x * G_BN;
    const size_t Kb = (size_t)K * 2;

    const char* gp[4] = {
        (const char*)Ahi + (size_t)row0 * Kb,
        (const char*)Alo + (size_t)row0 * Kb,
        (const char*)Bhi + (size_t)col0 * Kb,
        (const char*)Blo + (size_t)col0 * Kb
    };

    float acc[2][8][4];
#pragma unroll
    for (int mt = 0; mt < 2; mt++)
#pragma unroll
        for (int nt = 0; nt < 8; nt++)
#pragma unroll
            for (int r = 0; r < 4; r++) acc[mt][nt][r] = 0.0f;

    const int NCH = K / G_BK;

    auto load_chunk = [&](int c, int s) {
        size_t koff = (size_t)c * (G_BK * 2);
        uint32_t stb = sbase + s * STAGEB;
#pragma unroll
        for (int t = 0; t < 4; t++) {
            uint32_t tb = stb + t * TILEB;
            const char* g = gp[t];
#pragma unroll
            for (int i = 0; i < 2; i++) {
                int idx = i * 256 + tid;
                int row = idx >> 2;
                int ks  = idx & 3;
                cp16(tb + row * ROWB + ks * 16,
                     g + (size_t)row * Kb + koff + ks * 16);
            }
        }
    };

    load_chunk(0, 0);
    cp_commit();

    for (int c = 0; c < NCH; ++c) {
        const int buf = c & 1;
        cp_wait<0>();
        __syncthreads();
        if (c + 1 < NCH) {
            load_chunk(c + 1, buf ^ 1);
            cp_commit();
        }

        const uint32_t base = sbase + buf * STAGEB;
#pragma unroll
        for (int ks = 0; ks < 2; ks++) {
            uint32_t ah[2][4], al[2][4];
#pragma unroll
            for (int mt = 0; mt < 2; mt++) {
                uint32_t arow = wm * 32 + mt * 16 + (lane & 15);
                uint32_t aoff = arow * ROWB + (ks * 16 + 8 * (lane >> 4)) * 2;
                ldm_x4(ah[mt], base + aoff);
                ldm_x4(al[mt], base + TILEB + aoff);
            }
            uint32_t bh[8][2], bl[8][2];
#pragma unroll
            for (int p = 0; p < 4; p++) {
                uint32_t brow = wn * 64 + p * 16 + (lane & 7) + 8 * (lane >> 4);
                uint32_t boff = brow * ROWB + (ks * 16 + 8 * ((lane >> 3) & 1)) * 2;
                uint32_t t0[4], t1[4];
                ldm_x4(t0, base + 2 * TILEB + boff);
                ldm_x4(t1, base + 3 * TILEB + boff);
                bh[2*p][0]   = t0[0]; bh[2*p][1]   = t0[1];
                bh[2*p+1][0] = t0[2]; bh[2*p+1][1] = t0[3];
                bl[2*p][0]   = t1[0]; bl[2*p][1]   = t1[1];
                bl[2*p+1][0] = t1[2]; bl[2*p+1][1] = t1[3];
            }
#pragma unroll
            for (int mt = 0; mt < 2; mt++)
#pragma unroll
                for (int nt = 0; nt < 8; nt++) {
                    mma16816(acc[mt][nt], ah[mt], bh[nt]);
                    mma16816(acc[mt][nt], ah[mt], bl[nt]);
                    mma16816(acc[mt][nt], al[mt], bh[nt]);
                }
        }
        __syncthreads();
    }

#pragma unroll
    for (int mt = 0; mt < 2; mt++) {
        int r0 = row0 + wm * 32 + mt * 16 + (lane >> 2);
#pragma unroll
        for (int nt = 0; nt < 8; nt++) {
            int cc = col0 + wn * 64 + nt * 8 + (lane & 3) * 2;
            *(float2*)(C + (size_t)r0 * N + cc) =
                make_float2(acc[mt][nt][0], acc[mt][nt][1]);
            *(float2*)(C + (size_t)(r0 + 8) * N + cc) =
                make_float2(acc[mt][nt][2], acc[mt][nt][3]);
        }
    }
}

// ---------------------------------------------------------------------------
// Flash attention on mma.sync, bf16 hi/lo split for both GEMMs.
// CTA = 128 threads (4 warps x 16 rows), tile 64 q-rows x 64 k-rows.
// smem row stride 272 B -> conflict-free ldmatrix (68-word row walk).
// ---------------------------------------------------------------------------
#define F_ROWB 272
#define FT_BYTES (64 * F_ROWB)          // 17408 per tile
#define FLASH_SMEM (6 * FT_BYTES)       // 104448

__global__ __launch_bounds__(128, 2)
void flash_mma_kernel(const __nv_bfloat16* __restrict__ Qhi,
                      const __nv_bfloat16* __restrict__ Qlo,
                      const __nv_bfloat16* __restrict__ Khi,
                      const __nv_bfloat16* __restrict__ Klo,
                      const __nv_bfloat16* __restrict__ Vhi,
                      const __nv_bfloat16* __restrict__ Vlo,
                      __nv_bfloat16* __restrict__ Ohi,
                      __nv_bfloat16* __restrict__ Olo)
{
    extern __shared__ char sm_raw[];
    const uint32_t sb = smem_u32(sm_raw);
    const uint32_t sQh = sb,                sQl = sb + FT_BYTES;
    const uint32_t sKh = sb + 2*FT_BYTES,   sKl = sb + 3*FT_BYTES;
    const uint32_t sVh = sb + 4*FT_BYTES,   sVl = sb + 5*FT_BYTES;

    const int tid  = threadIdx.x;
    const int warp = tid >> 5;
    const int lane = tid & 31;
    const int lr   = lane >> 2;       // frag row within 8
    const int lc   = lane & 3;        // frag col pair
    const int m0   = warp * 16;

    const int mblk = blockIdx.x, h = blockIdx.y, b = blockIdx.z;
    const size_t qoff = ((size_t)(b * S_LEN + mblk * 64)) * INNER + h * HDIM;
    const size_t koff = ((size_t)(b * S_LEN)) * INNER + h * HDIM;

    // Q tiles (once)
#pragma unroll
    for (int i = 0; i < 8; i++) {
        int idx = i * 128 + tid;      // 0..1023
        int r = idx >> 4, s = idx & 15;
        uint32_t so = r * F_ROWB + s * 16;
        const size_t go = qoff + (size_t)r * INNER + s * 8;
        cp16(sQh + so, Qhi + go);
        cp16(sQl + so, Qlo + go);
    }
    cp_commit();

    float o[16][4];
#pragma unroll
    for (int nt = 0; nt < 16; nt++)
#pragma unroll
        for (int r = 0; r < 4; r++) o[nt][r] = 0.0f;
    float s_m[2] = { -1e30f, -1e30f };
    float s_l[2] = { 0.0f, 0.0f };
    const float scale = 0.08838834764831845f;

    // ldmatrix address offsets reused every iter
    const uint32_t a_row = m0 + (lane & 15);
    const uint32_t lhalf = 8 * (lane >> 4);

    for (int n0 = 0; n0 < S_LEN; n0 += 64) {
        // K/V tiles
#pragma unroll
        for (int i = 0; i < 8; i++) {
            int idx = i * 128 + tid;
            int r = idx >> 4, s = idx & 15;
            uint32_t so = r * F_ROWB + s * 16;
            const size_t go = koff + (size_t)(n0 + r) * INNER + s * 8;
            cp16(sKh + so, Khi + go);
            cp16(sKl + so, Klo + go);
            cp16(sVh + so, Vhi + go);
            cp16(sVl + so, Vlo + go);
        }
        cp_commit();
        cp_wait<0>();
        __syncthreads();

        // ---- S = Q @ K^T (hh + hl + lh) ----
        float s[8][4];
#pragma unroll
        for (int j = 0; j < 8; j++)
#pragma unroll
            for (int r = 0; r < 4; r++) s[j][r] = 0.0f;

#pragma unroll
        for (int t = 0; t < 8; t++) {
            const int d0 = t * 16;
            uint32_t ah[4], al[4];
            uint32_t aoff = a_row * F_ROWB + (d0 + lhalf) * 2;
            ldm_x4(ah, sQh + aoff);
            ldm_x4(al, sQl + aoff);
#pragma unroll
            for (int p = 0; p < 4; p++) {
                uint32_t bh[4], bl[4];
                uint32_t boff = (p * 16 + (lane & 15)) * F_ROWB + (d0 + lhalf) * 2;
                ldm_x4(bh, sKh + boff);
                ldm_x4(bl, sKl + boff);
                uint32_t b0h[2] = { bh[0], bh[2] }, b1h[2] = { bh[1], bh[3] };
                uint32_t b0l[2] = { bl[0], bl[2] }, b1l[2] = { bl[1], bl[3] };
                mma16816(s[2*p],   ah, b0h);
                mma16816(s[2*p],   ah, b0l);
                mma16816(s[2*p],   al, b0h);
                mma16816(s[2*p+1], ah, b1h);
                mma16816(s[2*p+1], ah, b1l);
                mma16816(s[2*p+1], al, b1h);
            }
        }

        // ---- online softmax ----
#pragma unroll
        for (int j = 0; j < 8; j++)
#pragma unroll
            for (int r = 0; r < 4; r++) s[j][r] *= scale;

        float mx0 = -1e30f, mx1 = -1e30f;
#pragma unroll
        for (int j = 0; j < 8; j++) {
            mx0 = fmaxf(mx0, fmaxf(s[j][0], s[j][1]));
            mx1 = fmaxf(mx1, fmaxf(s[j][2], s[j][3]));
        }
        mx0 = fmaxf(mx0, __shfl_xor_sync(0xffffffffu, mx0, 1));
        mx0 = fmaxf(mx0, __shfl_xor_sync(0xffffffffu, mx0, 2));
        mx1 = fmaxf(mx1, __shfl_xor_sync(0xffffffffu, mx1, 1));
        mx1 = fmaxf(mx1, __shfl_xor_sync(0xffffffffu, mx1, 2));

        float mn0 = fmaxf(s_m[0], mx0), mn1 = fmaxf(s_m[1], mx1);
        float al0 = __expf(s_m[0] - mn0), al1 = __expf(s_m[1] - mn1);
        s_m[0] = mn0; s_m[1] = mn1;

        float rs0 = 0.0f, rs1 = 0.0f;
#pragma unroll
        for (int j = 0; j < 8; j++) {
            s[j][0] = __expf(s[j][0] - mn0);
            s[j][1] = __expf(s[j][1] - mn0);
            s[j][2] = __expf(s[j][2] - mn1);
            s[j][3] = __expf(s[j][3] - mn1);
            rs0 += s[j][0] + s[j][1];
            rs1 += s[j][2] + s[j][3];
        }
        rs0 += __shfl_xor_sync(0xffffffffu, rs0, 1);
        rs0 += __shfl_xor_sync(0xffffffffu, rs0, 2);
        rs1 += __shfl_xor_sync(0xffffffffu, rs1, 1);
        rs1 += __shfl_xor_sync(0xffffffffu, rs1, 2);
        s_l[0] = s_l[0] * al0 + rs0;
        s_l[1] = s_l[1] * al1 + rs1;

#pragma unroll
        for (int nt = 0; nt < 16; nt++) {
            o[nt][0] *= al0; o[nt][1] *= al0;
            o[nt][2] *= al1; o[nt][3] *= al1;
        }

        // ---- pack P into bf16 hi/lo A-frags (register reuse, no smem) ----
        uint32_t ph[4][4], pl[4][4];
#pragma unroll
        for (int t = 0; t < 4; t++) {
#pragma unroll
            for (int q = 0; q < 4; q++) {
                int j = 2 * t + (q >> 1);
                int cc = (q & 1) * 2;
                float v0 = s[j][cc], v1 = s[j][cc + 1];
                __nv_bfloat16 h0 = __float2bfloat16(v0);
                __nv_bfloat16 h1 = __float2bfloat16(v1);
                float r0 = v0 - __bfloat162float(h0);
                float r1 = v1 - __bfloat162float(h1);
                __nv_bfloat162 hp; hp.x = h0; hp.y = h1;
                ph[t][q] = *(uint32_t*)&hp;
                pl[t][q] = pack_bf2(r0, r1);
            }
        }

        // ---- O += P @ V (hh + hl + lh) ----
#pragma unroll
        for (int t = 0; t < 4; t++) {
#pragma unroll
            for (int np = 0; np < 8; np++) {
                uint32_t vh[4], vl[4];
                uint32_t voff = (t * 16 + (lane & 15)) * F_ROWB + (np * 16 + lhalf) * 2;
                ldm_x4t(vh, sVh + voff);
                ldm_x4t(vl, sVl + voff);
                uint32_t b0h[2] = { vh[0], vh[1] }, b1h[2] = { vh[2], vh[3] };
                uint32_t b0l[2] = { vl[0], vl[1] }, b1l[2] = { vl[2], vl[3] };
                mma16816(o[2*np],   ph[t], b0h);
                mma16816(o[2*np],   ph[t], b0l);
                mma16816(o[2*np],   pl[t], b0h);
                mma16816(o[2*np+1], ph[t], b1h);
                mma16816(o[2*np+1], ph[t], b1l);
                mma16816(o[2*np+1], pl[t], b1h);
            }
        }
        __syncthreads();   // done reading K/V tiles before next iter's cp.async
    }

    // ---- epilogue: normalize, split to bf16 hi/lo, store ----
    float inv0 = 1.0f / s_l[0];
    float inv1 = 1.0f / s_l[1];
    size_t or0 = ((size_t)(b * S_LEN + mblk * 64 + m0 + lr)) * INNER + h * HDIM;
    size_t or1 = or0 + 8 * (size_t)INNER;
#pragma unroll
    for (int nt = 0; nt < 16; nt++) {
        int col = nt * 8 + lc * 2;
        float a0 = o[nt][0] * inv0, a1 = o[nt][1] * inv0;
        float b0 = o[nt][2] * inv1, b1 = o[nt][3] * inv1;
        __nv_bfloat16 h00 = __float2bfloat16(a0), h01 = __float2bfloat16(a1);
        __nv_bfloat16 h10 = __float2bfloat16(b0), h11 = __float2bfloat16(b1);
        __nv_bfloat162 hp0; hp0.x = h00; hp0.y = h01;
        __nv_bfloat162 hp1; hp1.x = h10; hp1.y = h11;
        *(uint32_t*)(Ohi + or0 + col) = *(uint32_t*)&hp0;
        *(uint32_t*)(Ohi + or1 + col) = *(uint32_t*)&hp1;
        *(uint32_t*)(Olo + or0 + col) =
            pack_bf2(a0 - __bfloat162float(h00), a1 - __bfloat162float(h01));
        *(uint32_t*)(Olo + or1 + col) =
            pack_bf2(b0 - __bfloat162float(h10), b1 - __bfloat162float(h11));
    }
}

// ---------------------------------------------------------------------------
// fp32 -> bf16 hi/lo split (elementwise)
// ---------------------------------------------------------------------------
__global__ void split_kernel(const float4* __restrict__ in,
                             __nv_bfloat16* __restrict__ hi,
                             __nv_bfloat16* __restrict__ lo, int n4) {
    int i = blockIdx.x * blockDim.x + threadIdx.x;
    if (i >= n4) return;
    float4 v = in[i];
    float f[4] = { v.x, v.y, v.z, v.w };
    __nv_bfloat16 h[4], l[4];
#pragma unroll
    for (int j = 0; j < 4; j++) {
        h[j] = __float2bfloat16(f[j]);
        l[j] = __float2bfloat16(f[j] - __bfloat162float(h[j]));
    }
    *(uint2*)(hi + 4 * (size_t)i) = *(uint2*)h;
    *(uint2*)(lo + 4 * (size_t)i) = *(uint2*)l;
}

// ---------------------------------------------------------------------------
// Fused RMSNorm (per 128-row) + bf16 hi/lo split. One warp per row.
// ---------------------------------------------------------------------------
__global__ void rmsnorm_split_kernel(const float* __restrict__ data,
                                     const float* __restrict__ gamma,
                                     __nv_bfloat16* __restrict__ hi,
                                     __nv_bfloat16* __restrict__ lo, int nrows) {
    int warp = (blockIdx.x * blockDim.x + threadIdx.x) >> 5;
    int lane = threadIdx.x & 31;
    if (warp >= nrows) return;
    const float* row = data + (size_t)warp * HDIM;
    float4 v = *(const float4*)(row + lane * 4);
    float ss = v.x * v.x + v.y * v.y + v.z * v.z + v.w * v.w;
#pragma unroll
    for (int ofs = 16; ofs > 0; ofs >>= 1)
        ss += __shfl_xor_sync(0xffffffffu, ss, ofs);
    float r = rsqrtf(ss * (1.0f / (float)HDIM) + 1e-6f);
    float4 g = *(const float4*)(gamma + lane * 4);
    float f[4] = { v.x * r * g.x, v.y * r * g.y, v.z * r * g.z, v.w * r * g.w };
    __nv_bfloat16 h[4], l[4];
#pragma unroll
    for (int j = 0; j < 4; j++) {
        h[j] = __float2bfloat16(f[j]);
        l[j] = __float2bfloat16(f[j] - __bfloat162float(h[j]));
    }
    size_t o = (size_t)warp * HDIM + lane * 4;
    *(uint2*)(hi + o) = *(uint2*)h;
    *(uint2*)(lo + o) = *(uint2*)l;
}

// ---------------------------------------------------------------------------
// Transpose + split: W[K, N] fp32 -> T{hi,lo}[N, K] bf16
// ---------------------------------------------------------------------------
__global__ void transpose_split_kernel(const float* __restrict__ W,
                                       __nv_bfloat16* __restrict__ Thi,
                                       __nv_bfloat16* __restrict__ Tlo) {
    __shared__ float t[32][33];
    int n0 = blockIdx.x * 32, k0 = blockIdx.y * 32;
#pragma unroll
    for (int i = 0; i < 32; i += 8)
        t[threadIdx.y + i][threadIdx.x] =
            W[(size_t)(k0 + threadIdx.y + i) * 2048 + n0 + threadIdx.x];
    __syncthreads();
#pragma unroll
    for (int i = 0; i < 32; i += 8) {
        float v = t[threadIdx.x][threadIdx.y + i];
        __nv_bfloat16 h = __float2bfloat16(v);
        __nv_bfloat16 l = __float2bfloat16(v - __bfloat162float(h));
        size_t o = (size_t)(n0 + threadIdx.y + i) * 2048 + k0 + threadIdx.x;
        Thi[o] = h;
        Tlo[o] = l;
    }
}

// ---------------------------------------------------------------------------
// Launcher
// ---------------------------------------------------------------------------
extern "C" void kernel_launch(void* const* d_in, const int* in_sizes, int n_in,
                              void* d_out, int out_size) {
    const float* x  = (const float*)d_in[0];
    const float* Wq = (const float*)d_in[1];
    const float* Wk = (const float*)d_in[2];
    const float* Wv = (const float*)d_in[3];
    const float* Wo = (const float*)d_in[4];
    const float* qg = (const float*)d_in[5];
    const float* kg = (const float*)d_in[6];
    float* out = (float*)d_out;

    float *dq, *dk, *dv;
    __nv_bfloat16 *xhi, *xlo, *wthi, *wtlo;
    __nv_bfloat16 *qhi, *qlo, *khi, *klo, *vhi, *vlo, *aohi, *aolo;
    cudaGetSymbolAddress((void**)&dq,   g_q);
    cudaGetSymbolAddress((void**)&dk,   g_k);
    cudaGetSymbolAddress((void**)&dv,   g_v);
    cudaGetSymbolAddress((void**)&xhi,  g_xhi);
    cudaGetSymbolAddress((void**)&xlo,  g_xlo);
    cudaGetSymbolAddress((void**)&wthi, g_wthi);
    cudaGetSymbolAddress((void**)&wtlo, g_wtlo);
    cudaGetSymbolAddress((void**)&qhi,  g_qhi);
    cudaGetSymbolAddress((void**)&qlo,  g_qlo);
    cudaGetSymbolAddress((void**)&khi,  g_khi);
    cudaGetSymbolAddress((void**)&klo,  g_klo);
    cudaGetSymbolAddress((void**)&vhi,  g_vhi);
    cudaGetSymbolAddress((void**)&vlo,  g_vlo);
    cudaGetSymbolAddress((void**)&aohi, g_aohi);
    cudaGetSymbolAddress((void**)&aolo, g_aolo);
    const size_t WSZ = (size_t)DMODEL * INNER;

    // 1. Split x -> bf16 hi/lo
    int n4x = ROWS * DMODEL / 4;
    split_kernel<<<n4x / 256, 256>>>((const float4*)x, xhi, xlo, n4x);

    // 2. Transpose+split weights
    dim3 tb(32, 8), tg(64, 64);
    transpose_split_kernel<<<tg, tb>>>(Wq, wthi + 0*WSZ, wtlo + 0*WSZ);
    transpose_split_kernel<<<tg, tb>>>(Wk, wthi + 1*WSZ, wtlo + 1*WSZ);
    transpose_split_kernel<<<tg, tb>>>(Wv, wthi + 2*WSZ, wtlo + 2*WSZ);
    transpose_split_kernel<<<tg, tb>>>(Wo, wthi + 3*WSZ, wtlo + 3*WSZ);

    // 3. QKV projections (tensor cores)
    cudaFuncSetAttribute(gemm_mma_kernel, cudaFuncAttributeMaxDynamicSharedMemorySize,
                         GEMM_SMEM);
    dim3 gg(INNER / G_BN, ROWS / G_BM);
    gemm_mma_kernel<<<gg, 256, GEMM_SMEM>>>(xhi, xlo, wthi + 0*WSZ, wtlo + 0*WSZ,
                                            dq, ROWS, INNER, DMODEL);
    gemm_mma_kernel<<<gg, 256, GEMM_SMEM>>>(xhi, xlo, wthi + 1*WSZ, wtlo + 1*WSZ,
                                            dk, ROWS, INNER, DMODEL);
    gemm_mma_kernel<<<gg, 256, GEMM_SMEM>>>(xhi, xlo, wthi + 2*WSZ, wtlo + 2*WSZ,
                                            dv, ROWS, INNER, DMODEL);

    // 4. RMSNorm + split q/k; split v
    int nrows = ROWS * NHEAD;
    int rb = (nrows * 32 + 255) / 256;
    rmsnorm_split_kernel<<<rb, 256>>>(dq, qg, qhi, qlo, nrows);
    rmsnorm_split_kernel<<<rb, 256>>>(dk, kg, khi, klo, nrows);
    int n4v = ROWS * INNER / 4;
    split_kernel<<<n4v / 256, 256>>>((const float4*)dv, vhi, vlo, n4v);

    // 5. Flash attention (mma.sync bf16 hi/lo) -> aohi/aolo directly
    cudaFuncSetAttribute(flash_mma_kernel, cudaFuncAttributeMaxDynamicSharedMemorySize,
                         FLASH_SMEM);
    dim3 gridF(S_LEN / 64, NHEAD, BATCH);
    flash_mma_kernel<<<gridF, 128, FLASH_SMEM>>>(qhi, qlo, khi, klo, vhi, vlo,
                                                 aohi, aolo);

    // 6. Output projection -> d_out
    gemm_mma_kernel<<<gg, 256, GEMM_SMEM>>>(aohi, aolo, wthi + 3*WSZ, wtlo + 3*WSZ,
                                            out, ROWS, DMODEL, INNER);
}